// round 1
// baseline (speedup 1.0000x reference)
#include <cuda_runtime.h>
#include <cstdint>

// Problem constants (fixed by the reference setup)
#define BB       256
#define II       1024
#define PP       128
#define HH       128
#define LPROT    1024

// Dynamic smem layout (floats):
//   acc   : 128*128        = 16384   (64 KB)  per-batch output accumulator
//   cgate : 4*256          = 1024    (4 KB)   compacted gates, per source warp
//   cidx  : 4*256 (uint)   = 1024    (4 KB)   packed (il | ip<<16)
//   cnt   : 4 (int)
static const int ACC_ELEMS   = 128 * HH;        // 16384
static const int CGATE_OFF   = ACC_ELEMS;       // 16384
static const int CIDX_OFF    = CGATE_OFF + 1024;
static const int CNT_OFF     = CIDX_OFF + 1024;
static const int SMEM_FLOATS = CNT_OFF + 4;
static const int SMEM_BYTES  = SMEM_FLOATS * 4; // 73744 bytes

__global__ __launch_bounds__(128)
void ile_kernel(const float* __restrict__ param_enc,
                const float* __restrict__ h_prot,
                const float* __restrict__ w1,
                const float* __restrict__ b1,
                const int*   __restrict__ idx_lig,
                const int*   __restrict__ idx_prot,
                const int*   __restrict__ protein_idx,
                const int*   __restrict__ lig_offsets,
                float*       __restrict__ out)
{
    extern __shared__ float smem[];
    float*        acc   = smem;
    float*        cgate = smem + CGATE_OFF;
    unsigned int* cidx  = reinterpret_cast<unsigned int*>(smem + CIDX_OFF);
    int*          cnt   = reinterpret_cast<int*>(smem + CNT_OFF);

    const int b    = blockIdx.x;
    const int tid  = threadIdx.x;
    const int wid  = tid >> 5;     // 0..3
    const int lane = tid & 31;

    // ---- zero the accumulator (16384 floats, float4 stores) ----
    {
        float4 z = make_float4(0.f, 0.f, 0.f, 0.f);
        float4* a4 = reinterpret_cast<float4*>(acc);
        #pragma unroll
        for (int k = 0; k < ACC_ELEMS / 4 / 128; k++)
            a4[tid + k * 128] = z;
    }

    // ---- preload w1 (each lane holds 4 consecutive weights) and bias ----
    const float4 wv  = reinterpret_cast<const float4*>(w1)[lane];
    const float bias = b1[0];

    const float* pe   = param_enc + (size_t)b * II * PP;
    const int*   il_b = idx_lig  + b * II;
    const int*   ip_b = idx_prot + b * II;

    // =====================================================================
    // Phase 1: gate GEMV + relu + deterministic ballot compaction.
    // Warp `wid` handles rows [wid*256, wid*256+256). For each row the warp
    // does a coalesced 512B float4 load + butterfly reduce; after a group of
    // 32 rows each lane keeps the gate of row (base + lane), then the warp
    // ballot-compacts survivors (gate > 0) into its private list.
    // =====================================================================
    int wcount = 0;
    const int rowbase = wid * 256;
    for (int grp = 0; grp < 256; grp += 32) {
        float mygate = 0.f;
        #pragma unroll 8
        for (int r = 0; r < 32; r++) {
            const int row = rowbase + grp + r;
            float4 v = reinterpret_cast<const float4*>(pe + (size_t)row * PP)[lane];
            float s = v.x * wv.x + v.y * wv.y + v.z * wv.z + v.w * wv.w;
            s += __shfl_xor_sync(0xffffffffu, s, 16);
            s += __shfl_xor_sync(0xffffffffu, s, 8);
            s += __shfl_xor_sync(0xffffffffu, s, 4);
            s += __shfl_xor_sync(0xffffffffu, s, 2);
            s += __shfl_xor_sync(0xffffffffu, s, 1);
            const float g = s + bias;          // relu happens via the g>0 filter
            if (lane == r) mygate = g;
        }
        const int row = rowbase + grp + lane;
        const bool act = (mygate > 0.f);
        const unsigned bal = __ballot_sync(0xffffffffu, act);
        const int pos = wcount + __popc(bal & ((1u << lane) - 1u));
        if (act) {
            cgate[wid * 256 + pos] = mygate;
            cidx [wid * 256 + pos] = (unsigned)il_b[row] | ((unsigned)ip_b[row] << 16);
        }
        wcount += __popc(bal);
    }
    if (lane == 0) cnt[wid] = wcount;
    __syncthreads();

    // =====================================================================
    // Phase 2: gather + scaled accumulate. Warp `wid` owns H columns
    // [wid*32, wid*32+32); each thread exclusively owns one output column,
    // so plain (non-atomic) smem read-modify-write is race-free.
    // =====================================================================
    {
        const int pb = protein_idx[b];
        const float* hp  = h_prot + (size_t)pb * LPROT * HH;
        const int colbase = wid * 32;
        float*       accw = acc + colbase + lane;
        const float* hpc  = hp  + colbase + lane;

        #pragma unroll
        for (int w = 0; w < 4; w++) {
            const int n = cnt[w];
            const float*        gl = cgate + w * 256;
            const unsigned int* xl = cidx  + w * 256;
            #pragma unroll 4
            for (int j = 0; j < n; j++) {
                const float    g   = gl[j];
                const unsigned ix  = xl[j];
                const int il = (int)(ix & 0xffffu);
                const int ip = (int)(ix >> 16);
                const float val = __ldg(hpc + ip * HH);
                accw[il * HH] += g * val;     // column-exclusive: no race
            }
        }
    }
    __syncthreads();

    // ---- Phase 3: coalesced writeout of this batch's 128x128 slice ----
    {
        const int off = lig_offsets[b];
        float4*       o4 = reinterpret_cast<float4*>(out + (size_t)off * HH);
        const float4* a4 = reinterpret_cast<const float4*>(acc);
        #pragma unroll
        for (int k = 0; k < ACC_ELEMS / 4 / 128; k++)
            o4[tid + k * 128] = a4[tid + k * 128];
    }
}

extern "C" void kernel_launch(void* const* d_in, const int* in_sizes, int n_in,
                              void* d_out, int out_size)
{
    // Inputs in metadata order:
    // 0 param_enc f32 [256,1024,128]   1 h_prot f32 [256,1024,128]
    // 2 w1 f32 [128,1]                 3 b1 f32 [1]
    // 4 indices_lig i32 [256,1024]     5 indices_prot i32 [256,1024]
    // 6 protein_idx i32 [256]          7 lig_offsets i32 [256]
    // 8 mask bool [256,1024]  (all-true by construction; not read)
    (void)in_sizes; (void)n_in; (void)out_size;

    cudaFuncSetAttribute(ile_kernel,
                         cudaFuncAttributeMaxDynamicSharedMemorySize, SMEM_BYTES);

    ile_kernel<<<BB, 128, SMEM_BYTES>>>(
        (const float*)d_in[0], (const float*)d_in[1],
        (const float*)d_in[2], (const float*)d_in[3],
        (const int*)d_in[4],   (const int*)d_in[5],
        (const int*)d_in[6],   (const int*)d_in[7],
        (float*)d_out);
}

// round 2
// speedup vs baseline: 4.2364x; 4.2364x over previous
#include <cuda_runtime.h>
#include <cstdint>

#define BB     256
#define II     1024
#define PP     128
#define HH     128
#define LPROT  1024

// Dynamic smem layout (floats). Tile region is UNIONED with the accumulator:
//  [0, 16896)        tile: 128 rows x 132 floats (padded)  |  acc: 128x128 (phase 2/3)
//  [16896, 17024)    w1 copy (128)
//  [17024, 17280)    psum (2 x 128)
//  [17280, 19328)    ent: 1024 x float2 {gate, packed idx}
//  [19328, 20352)    wlist: 8 warps x 256 uint16 (4 KB)
static const int TILE_F   = 128 * 132;   // 16896
static const int WS_OFF   = TILE_F;                 // 16896
static const int PS_OFF   = WS_OFF + 128;           // 17024
static const int ENT_OFF  = PS_OFF + 256;           // 17280
static const int WL_OFF   = ENT_OFF + 2048;         // 19328
static const int SMEM_F   = WL_OFF + 1024;          // 20352
static const int SMEM_B   = SMEM_F * 4;             // 81408 bytes

__global__ __launch_bounds__(256, 2)
void ile_kernel(const float* __restrict__ param_enc,
                const float* __restrict__ h_prot,
                const float* __restrict__ w1,
                const float* __restrict__ b1,
                const int*   __restrict__ idx_lig,
                const int*   __restrict__ idx_prot,
                const int*   __restrict__ protein_idx,
                const int*   __restrict__ lig_offsets,
                float*       __restrict__ out)
{
    extern __shared__ float sm[];
    float*          tile  = sm;                       // phase 1
    float*          acc   = sm;                       // phase 2/3 (union)
    float*          wsm   = sm + WS_OFF;
    float*          psum  = sm + PS_OFF;
    float2*         ent   = reinterpret_cast<float2*>(sm + ENT_OFF);
    unsigned short* wlist = reinterpret_cast<unsigned short*>(sm + WL_OFF);

    const int b    = blockIdx.x;
    const int tid  = threadIdx.x;
    const int wid  = tid >> 5;      // 0..7
    const int lane = tid & 31;

    if (tid < 128) wsm[tid] = w1[tid];
    const float bias = b1[0];
    __syncthreads();

    const float* pe   = param_enc + (size_t)b * II * PP;
    const int*   il_b = idx_lig  + b * II;
    const int*   ip_b = idx_prot + b * II;

    // =====================================================================
    // Phase 1: gates via smem-staged tiles (no shuffles).
    // 8 tiles of 128 rows. Per tile: each warp stages 16 rows coalesced
    // (LDG.128 issued BEFORE the barrier -> overlaps previous compute),
    // then each thread computes half a row (64 cols) from smem.
    // =====================================================================
    const int r_half = tid & 127;
    const int hhalf  = tid >> 7;    // 0 or 1

    for (int t8 = 0; t8 < 8; t8++) {
        const int rowbase = t8 * 128 + wid * 16;
        float4 st[16];
        #pragma unroll
        for (int k = 0; k < 16; k++)
            st[k] = reinterpret_cast<const float4*>(pe + (size_t)(rowbase + k) * PP)[lane];

        __syncthreads();   // previous tile fully consumed
        #pragma unroll
        for (int k = 0; k < 16; k++)
            *reinterpret_cast<float4*>(tile + (wid * 16 + k) * 132 + 4 * lane) = st[k];
        __syncthreads();

        const float* trow = tile + r_half * 132 + 64 * hhalf;
        const float* wrow = wsm + 64 * hhalf;
        float s = 0.f;
        #pragma unroll
        for (int k = 0; k < 16; k++) {
            float4 v = *reinterpret_cast<const float4*>(trow + 4 * k);
            float4 w = *reinterpret_cast<const float4*>(wrow + 4 * k);
            s += v.x * w.x + v.y * w.y + v.z * w.z + v.w * w.w;
        }
        psum[hhalf * 128 + r_half] = s;
        __syncthreads();

        if (tid < 128) {
            const int row = t8 * 128 + tid;
            const float g = psum[tid] + psum[128 + tid] + bias;
            const unsigned ix = (unsigned)il_b[row] | ((unsigned)ip_b[row] << 16);
            ent[row] = make_float2(g, __uint_as_float(ix));
        }
        // next iteration's first barrier orders psum/tile reuse
    }
    __syncthreads();   // all ent written; tile no longer read

    // ---- zero the accumulator (reuses tile region) ----
    {
        float4 z = make_float4(0.f, 0.f, 0.f, 0.f);
        float4* a4 = reinterpret_cast<float4*>(acc);
        #pragma unroll
        for (int k = 0; k < 16; k++)
            a4[tid + 256 * k] = z;
    }
    __syncthreads();

    // =====================================================================
    // Phase 2: gather + accumulate. Warp `wid` owns output rows with
    // il>>4 == wid (16 rows) -> race-free. Lane owns 4 columns (float4).
    // Per 256-entry block: ballot-compact my entries, then process in
    // batches of 8 for MLP=8 on the h_prot gathers.
    // =====================================================================
    {
        const int pb = protein_idx[b];
        const float* hp = h_prot + (size_t)pb * LPROT * HH;
        unsigned short* wl = wlist + wid * 256;

        for (int blk = 0; blk < 4; blk++) {
            // pass A: compact
            int cnt = 0;
            #pragma unroll
            for (int j0 = blk * 256; j0 < blk * 256 + 256; j0 += 32) {
                float2 e = ent[j0 + lane];
                unsigned ix = __float_as_uint(e.y);
                bool mine = (e.x > 0.f) && (((ix & 0xffffu) >> 4) == (unsigned)wid);
                unsigned bal = __ballot_sync(0xffffffffu, mine);
                int pos = cnt + __popc(bal & ((1u << lane) - 1u));
                if (mine) wl[pos] = (unsigned short)(j0 + lane);
                cnt += __popc(bal);
            }
            // pass B: batched processing, 8 gathers in flight
            for (int i = 0; i < cnt; i += 8) {
                float  gq[8];
                int    ilq[8];
                float4 hq[8];
                #pragma unroll
                for (int q = 0; q < 8; q++) {
                    const bool v = (i + q) < cnt;
                    const int jj = v ? (int)wl[i + q] : (int)wl[i];  // valid fallback
                    float2 e = ent[jj];
                    unsigned ix = __float_as_uint(e.y);
                    gq[q]  = v ? e.x : 0.f;
                    ilq[q] = (int)(ix & 0xffffu);
                    const int ip = (int)(ix >> 16);
                    hq[q] = *reinterpret_cast<const float4*>(hp + (size_t)ip * HH + 4 * lane);
                }
                #pragma unroll
                for (int q = 0; q < 8; q++) {
                    float4* ap = reinterpret_cast<float4*>(acc + ilq[q] * HH + 4 * lane);
                    float4 a = *ap;
                    a.x += gq[q] * hq[q].x;
                    a.y += gq[q] * hq[q].y;
                    a.z += gq[q] * hq[q].z;
                    a.w += gq[q] * hq[q].w;
                    *ap = a;
                }
            }
        }
    }
    __syncthreads();

    // ---- Phase 3: coalesced writeout ----
    {
        const int off = lig_offsets[b];
        float4*       o4 = reinterpret_cast<float4*>(out + (size_t)off * HH);
        const float4* a4 = reinterpret_cast<const float4*>(acc);
        #pragma unroll
        for (int k = 0; k < 16; k++)
            o4[tid + 256 * k] = a4[tid + 256 * k];
    }
}

extern "C" void kernel_launch(void* const* d_in, const int* in_sizes, int n_in,
                              void* d_out, int out_size)
{
    (void)in_sizes; (void)n_in; (void)out_size;

    cudaFuncSetAttribute(ile_kernel,
                         cudaFuncAttributeMaxDynamicSharedMemorySize, SMEM_B);

    ile_kernel<<<BB, 256, SMEM_B>>>(
        (const float*)d_in[0], (const float*)d_in[1],
        (const float*)d_in[2], (const float*)d_in[3],
        (const int*)d_in[4],   (const int*)d_in[5],
        (const int*)d_in[6],   (const int*)d_in[7],
        (float*)d_out);
}

// round 3
// speedup vs baseline: 4.3352x; 1.0233x over previous
#include <cuda_runtime.h>
#include <cstdint>

#define BB     256
#define II     1024
#define PP     128
#define HH     128
#define LPROT  1024

// Dynamic smem layout (floats):
//  [0, 16896)   phase1: 2 x (64 rows x 132 floats) cp.async tile double-buffer
//               phase2/3: acc 128x128 (16384 floats) -- UNION
//  [16896, 18944)  ent: 1024 x float2 {gate, packed (il | ip<<16)}
//  [18944, 19968)  wlist: 16 warps x 256 uint8 block-offsets (4096 B)
static const int TILE_ROWS  = 64;
static const int TILE_STR   = 132;                  // padded row stride (floats)
static const int TILE_F     = TILE_ROWS * TILE_STR; // 8448 per buffer
static const int UNION_F    = 2 * TILE_F;           // 16896 >= acc 16384
static const int ENT_OFF    = UNION_F;              // 16896
static const int WL_OFF     = ENT_OFF + 2048;       // 18944
static const int SMEM_F     = WL_OFF + 1024;        // 19968
static const int SMEM_B     = SMEM_F * 4;           // 79872 bytes

__device__ __forceinline__ uint32_t smem_u32(const void* p) {
    uint32_t a;
    asm("{ .reg .u64 t; cvta.to.shared.u64 t, %1; cvt.u32.u64 %0, t; }"
        : "=r"(a) : "l"(p));
    return a;
}
__device__ __forceinline__ void cp_async16(uint32_t dst, const void* src) {
    asm volatile("cp.async.cg.shared.global [%0], [%1], 16;"
                 :: "r"(dst), "l"(src));
}
__device__ __forceinline__ void cp_commit() {
    asm volatile("cp.async.commit_group;");
}
template <int N>
__device__ __forceinline__ void cp_wait() {
    asm volatile("cp.async.wait_group %0;" :: "n"(N));
}

__global__ __launch_bounds__(512, 2)
void ile_kernel(const float* __restrict__ param_enc,
                const float* __restrict__ h_prot,
                const float* __restrict__ w1,
                const float* __restrict__ b1,
                const int*   __restrict__ idx_lig,
                const int*   __restrict__ idx_prot,
                const int*   __restrict__ protein_idx,
                const int*   __restrict__ lig_offsets,
                float*       __restrict__ out)
{
    extern __shared__ float sm[];
    float*         tile0 = sm;                 // phase 1 buffers
    float*         acc   = sm;                 // phase 2/3 (union)
    float2*        ent   = reinterpret_cast<float2*>(sm + ENT_OFF);
    unsigned char* wlist = reinterpret_cast<unsigned char*>(sm + WL_OFF);

    const int b    = blockIdx.x;
    const int tid  = threadIdx.x;
    const int wid  = tid >> 5;      // 0..15
    const int lane = tid & 31;
    const int e8   = lane & 7;      // column-eighth within row
    const int rsub = lane >> 3;     // row-within-warp (0..3)

    const float bias = b1[0];
    // per-thread w1 slice: cols 4*(e8 + 8k), k=0..3  -> 16 registers, loaded once
    float4 wreg[4];
    #pragma unroll
    for (int k = 0; k < 4; k++)
        wreg[k] = *reinterpret_cast<const float4*>(w1 + 4 * e8 + 32 * k);

    const float* pe   = param_enc + (size_t)b * II * PP;
    const int*   il_b = idx_lig  + b * II;
    const int*   ip_b = idx_prot + b * II;

    // =====================================================================
    // Phase 1: gates via cp.async double-buffered 64-row tiles (16 tiles).
    // =====================================================================
    {
        // stage tile t into buffer (t&1): 2048 float4, 4 per thread, coalesced
        auto stage = [&](int t) {
            const float* src = pe + (size_t)t * TILE_ROWS * PP;
            float* dst = tile0 + (t & 1) * TILE_F;
            #pragma unroll
            for (int k = 0; k < 4; k++) {
                const int idx = tid + 512 * k;      // 0..2047
                const int r  = idx >> 5;            // row 0..63
                const int c4 = idx & 31;            // float4 col
                cp_async16(smem_u32(dst + r * TILE_STR + 4 * c4),
                           src + r * PP + 4 * c4);
            }
            cp_commit();
        };

        stage(0);
        for (int t = 0; t < 16; t++) {
            if (t < 15) stage(t + 1);
            if (t < 15) cp_wait<1>(); else cp_wait<0>();
            __syncthreads();                         // tile t visible to all

            // compute: warp w owns tile rows [4w, 4w+4); thread handles 16 cols
            const float* trow = tile0 + (t & 1) * TILE_F
                              + (4 * wid + rsub) * TILE_STR + 4 * e8;
            float s = 0.f;
            #pragma unroll
            for (int k = 0; k < 4; k++) {
                float4 v = *reinterpret_cast<const float4*>(trow + 32 * k);
                s += v.x * wreg[k].x + v.y * wreg[k].y
                   + v.z * wreg[k].z + v.w * wreg[k].w;
            }
            s += __shfl_xor_sync(0xffffffffu, s, 1);
            s += __shfl_xor_sync(0xffffffffu, s, 2);
            s += __shfl_xor_sync(0xffffffffu, s, 4);
            if (e8 == 0) {
                const int row = t * TILE_ROWS + 4 * wid + rsub;
                const unsigned ix = (unsigned)il_b[row] | ((unsigned)ip_b[row] << 16);
                ent[row] = make_float2(s + bias, __uint_as_float(ix));
            }
            __syncthreads();                         // buf reusable next+1 iter
        }
    }

    // ---- zero the accumulator (reuses tile region) ----
    {
        float4 z = make_float4(0.f, 0.f, 0.f, 0.f);
        float4* a4 = reinterpret_cast<float4*>(acc);
        #pragma unroll
        for (int k = 0; k < 8; k++)
            a4[tid + 512 * k] = z;
    }
    __syncthreads();

    // =====================================================================
    // Phase 2: gather + accumulate. Warp `wid` owns output rows with
    // il>>3 == wid (8 rows, race-free). Lane owns 4 cols (float4).
    // Batches of 4 gathers in flight.
    // =====================================================================
    {
        const int pb = protein_idx[b];
        const float* hp = h_prot + (size_t)pb * LPROT * HH;
        unsigned char* wl = wlist + wid * 256;

        for (int blk = 0; blk < 4; blk++) {
            const int j0b = blk * 256;
            // pass A: ballot-compact my entries (deterministic order)
            int cnt = 0;
            #pragma unroll
            for (int j0 = j0b; j0 < j0b + 256; j0 += 32) {
                float2 e = ent[j0 + lane];
                unsigned ix = __float_as_uint(e.y);
                bool mine = (e.x > 0.f) && (((ix & 0xffffu) >> 3) == (unsigned)wid);
                unsigned bal = __ballot_sync(0xffffffffu, mine);
                int pos = cnt + __popc(bal & ((1u << lane) - 1u));
                if (mine) wl[pos] = (unsigned char)(j0 + lane - j0b);
                cnt += __popc(bal);
            }
            // pass B: batched processing, 4 gathers in flight
            for (int i = 0; i < cnt; i += 4) {
                float  gq[4];
                int    ilq[4];
                float4 hq[4];
                #pragma unroll
                for (int q = 0; q < 4; q++) {
                    const bool v = (i + q) < cnt;
                    const int jj = j0b + (int)wl[v ? (i + q) : i];
                    float2 e = ent[jj];
                    unsigned ix = __float_as_uint(e.y);
                    gq[q]  = v ? e.x : 0.f;
                    ilq[q] = (int)(ix & 0xffffu);
                    const int ip = (int)(ix >> 16);
                    hq[q] = *reinterpret_cast<const float4*>(hp + (size_t)ip * HH + 4 * lane);
                }
                #pragma unroll
                for (int q = 0; q < 4; q++) {
                    float4* ap = reinterpret_cast<float4*>(acc + ilq[q] * HH + 4 * lane);
                    float4 a = *ap;
                    a.x += gq[q] * hq[q].x;
                    a.y += gq[q] * hq[q].y;
                    a.z += gq[q] * hq[q].z;
                    a.w += gq[q] * hq[q].w;
                    *ap = a;
                }
            }
        }
    }
    __syncthreads();

    // ---- Phase 3: coalesced writeout ----
    {
        const int off = lig_offsets[b];
        float4*       o4 = reinterpret_cast<float4*>(out + (size_t)off * HH);
        const float4* a4 = reinterpret_cast<const float4*>(acc);
        #pragma unroll
        for (int k = 0; k < 8; k++)
            o4[tid + 512 * k] = a4[tid + 512 * k];
    }
}

extern "C" void kernel_launch(void* const* d_in, const int* in_sizes, int n_in,
                              void* d_out, int out_size)
{
    (void)in_sizes; (void)n_in; (void)out_size;

    cudaFuncSetAttribute(ile_kernel,
                         cudaFuncAttributeMaxDynamicSharedMemorySize, SMEM_B);

    ile_kernel<<<BB, 512, SMEM_B>>>(
        (const float*)d_in[0], (const float*)d_in[1],
        (const float*)d_in[2], (const float*)d_in[3],
        (const int*)d_in[4],   (const int*)d_in[5],
        (const int*)d_in[6],   (const int*)d_in[7],
        (float*)d_out);
}

// round 4
// speedup vs baseline: 4.9878x; 1.1505x over previous
#include <cuda_runtime.h>
#include <cstdint>

#define BB     256
#define II     1024
#define PP     128
#define HH     128
#define LPROT  1024

// smem: ent 1024 x float2 (8 KB) + wlist 16 warps x 256 bytes (4 KB)
static const int WL_OFF  = 2048;            // floats
static const int SMEM_F  = WL_OFF + 1024;
static const int SMEM_B  = SMEM_F * 4;      // 12288 bytes

__global__ __launch_bounds__(512, 2)
void ile_kernel(const float* __restrict__ param_enc,
                const float* __restrict__ h_prot,
                const float* __restrict__ w1,
                const float* __restrict__ b1,
                const int*   __restrict__ idx_lig,
                const int*   __restrict__ idx_prot,
                const int*   __restrict__ protein_idx,
                const int*   __restrict__ lig_offsets,
                float*       __restrict__ out)
{
    extern __shared__ float sm[];
    float2*        ent   = reinterpret_cast<float2*>(sm);
    unsigned char* wlist = reinterpret_cast<unsigned char*>(sm + WL_OFF);

    const int b    = blockIdx.x;
    const int tid  = threadIdx.x;
    const int wid  = tid >> 5;      // 0..15
    const int lane = tid & 31;
    const int e8   = lane & 7;      // column-eighth
    const int rsub = lane >> 3;     // row-within-warp (0..3)

    const float* pe   = param_enc + (size_t)b * II * PP;
    const int*   il_b = idx_lig  + b * II;
    const int*   ip_b = idx_prot + b * II;

    // ---- startup: pack (il | ip<<16) into ent[].y, coalesced ----
    #pragma unroll
    for (int k = 0; k < 2; k++) {
        const int row = tid + 512 * k;
        ent[row].y = __uint_as_float((unsigned)il_b[row]
                                   | ((unsigned)ip_b[row] << 16));
    }

    // ---- phase 1: gates via DIRECT coalesced LDG.128 (no staging) ----
    const float bias = b1[0];
    float4 wreg[4];
    #pragma unroll
    for (int k = 0; k < 4; k++)
        wreg[k] = *reinterpret_cast<const float4*>(w1 + 4 * e8 + 32 * k);

    for (int t = 0; t < 16; t++) {
        const int row = t * 64 + 4 * wid + rsub;
        const float* pr = pe + (size_t)row * PP + 4 * e8;
        float4 v0 = *reinterpret_cast<const float4*>(pr);
        float4 v1 = *reinterpret_cast<const float4*>(pr + 32);
        float4 v2 = *reinterpret_cast<const float4*>(pr + 64);
        float4 v3 = *reinterpret_cast<const float4*>(pr + 96);
        float s = v0.x * wreg[0].x + v0.y * wreg[0].y + v0.z * wreg[0].z + v0.w * wreg[0].w
                + v1.x * wreg[1].x + v1.y * wreg[1].y + v1.z * wreg[1].z + v1.w * wreg[1].w
                + v2.x * wreg[2].x + v2.y * wreg[2].y + v2.z * wreg[2].z + v2.w * wreg[2].w
                + v3.x * wreg[3].x + v3.y * wreg[3].y + v3.z * wreg[3].z + v3.w * wreg[3].w;
        s += __shfl_xor_sync(0xffffffffu, s, 1);
        s += __shfl_xor_sync(0xffffffffu, s, 2);
        s += __shfl_xor_sync(0xffffffffu, s, 4);
        if (e8 == 0) ent[row].x = s + bias;
    }
    __syncthreads();

    // ---- phase 2: gather + REGISTER accumulate ----
    // Warp owns output rows with il>>3 == wid; lane owns 4 cols (float4).
    // acc[r] = row 8*wid + r. All lanes process the same entry -> il&7 is
    // warp-uniform -> non-divergent switch selects the register.
    float4 acc[8];
    #pragma unroll
    for (int r = 0; r < 8; r++) acc[r] = make_float4(0.f, 0.f, 0.f, 0.f);

    {
        const int pb = protein_idx[b];
        const float* hp = h_prot + (size_t)pb * LPROT * HH + 4 * lane;
        unsigned char* wl = wlist + wid * 256;

        for (int blk = 0; blk < 4; blk++) {
            const int j0b = blk * 256;
            // pass A: ballot-compact my entries (deterministic order)
            int cnt = 0;
            #pragma unroll
            for (int j0 = 0; j0 < 256; j0 += 32) {
                float2 e = ent[j0b + j0 + lane];
                unsigned ix = __float_as_uint(e.y);
                bool mine = (e.x > 0.f) && (((ix & 0xffffu) >> 3) == (unsigned)wid);
                unsigned bal = __ballot_sync(0xffffffffu, mine);
                int pos = cnt + __popc(bal & ((1u << lane) - 1u));
                if (mine) wl[pos] = (unsigned char)(j0 + lane);
                cnt += __popc(bal);
            }
            // pass B: batches of 4 gathers in flight
            for (int i = 0; i < cnt; i += 4) {
                float    gq[4];
                unsigned ilp = 0;
                float4   hq[4];
                #pragma unroll
                for (int q = 0; q < 4; q++) {
                    const bool v = (i + q) < cnt;
                    const int jj = j0b + (int)wl[v ? (i + q) : i];
                    float2 e = ent[jj];
                    unsigned ix = __float_as_uint(e.y);
                    gq[q] = v ? e.x : 0.f;
                    ilp |= (ix & 7u) << (8 * q);
                    hq[q] = *reinterpret_cast<const float4*>(hp + (size_t)(ix >> 16) * HH);
                }
                #pragma unroll
                for (int q = 0; q < 4; q++) {
                    const float  g = gq[q];
                    const float4 h = hq[q];
                    #define ACC_CASE(R) case R: \
                        acc[R].x += g * h.x; acc[R].y += g * h.y; \
                        acc[R].z += g * h.z; acc[R].w += g * h.w; break;
                    switch ((ilp >> (8 * q)) & 7u) {
                        ACC_CASE(0) ACC_CASE(1) ACC_CASE(2) ACC_CASE(3)
                        ACC_CASE(4) ACC_CASE(5) ACC_CASE(6) ACC_CASE(7)
                    }
                    #undef ACC_CASE
                }
            }
        }
    }

    // ---- phase 3: direct register -> global writeout (coalesced) ----
    {
        const int off = lig_offsets[b];
        float* ob = out + (size_t)off * HH + 4 * lane;
        #pragma unroll
        for (int r = 0; r < 8; r++)
            *reinterpret_cast<float4*>(ob + (8 * wid + r) * HH) = acc[r];
    }
}

extern "C" void kernel_launch(void* const* d_in, const int* in_sizes, int n_in,
                              void* d_out, int out_size)
{
    (void)in_sizes; (void)n_in; (void)out_size;

    cudaFuncSetAttribute(ile_kernel,
                         cudaFuncAttributeMaxDynamicSharedMemorySize, SMEM_B);

    ile_kernel<<<BB, 512, SMEM_B>>>(
        (const float*)d_in[0], (const float*)d_in[1],
        (const float*)d_in[2], (const float*)d_in[3],
        (const int*)d_in[4],   (const int*)d_in[5],
        (const int*)d_in[6],   (const int*)d_in[7],
        (float*)d_out);
}

// round 5
// speedup vs baseline: 5.8999x; 1.1829x over previous
#include <cuda_runtime.h>
#include <cstdint>

#define BB     256
#define II     1024
#define PP     128
#define HH     128
#define LPROT  1024

// smem: ent 1024 x float2 (8 KB) + wlist 16 warps x 256 bytes (4 KB)
static const int WL_OFF  = 2048;            // floats
static const int SMEM_F  = WL_OFF + 1024;
static const int SMEM_B  = SMEM_F * 4;      // 12288 bytes

__global__ __launch_bounds__(512, 2)
void ile_kernel(const float* __restrict__ param_enc,
                const float* __restrict__ h_prot,
                const float* __restrict__ w1,
                const float* __restrict__ b1,
                const int*   __restrict__ idx_lig,
                const int*   __restrict__ idx_prot,
                const int*   __restrict__ protein_idx,
                const int*   __restrict__ lig_offsets,
                float*       __restrict__ out)
{
    extern __shared__ float sm[];
    float2*        ent   = reinterpret_cast<float2*>(sm);
    unsigned char* wlist = reinterpret_cast<unsigned char*>(sm + WL_OFF);

    const int b    = blockIdx.x;
    const int tid  = threadIdx.x;
    const int wid  = tid >> 5;      // 0..15
    const int lane = tid & 31;
    const int e8   = lane & 7;      // column-eighth
    const int rsub = lane >> 3;     // row-within-warp (0..3)

    const float* pe   = param_enc + (size_t)b * II * PP;
    const int*   il_b = idx_lig  + b * II;
    const int*   ip_b = idx_prot + b * II;

    // ---- startup: pack (il | ip<<16) into ent[].y, coalesced ----
    #pragma unroll
    for (int k = 0; k < 2; k++) {
        const int row = tid + 512 * k;
        ent[row].y = __uint_as_float((unsigned)il_b[row]
                                   | ((unsigned)ip_b[row] << 16));
    }

    // ---- phase 1: gates via direct LDG.128, ping-pong pipelined ----
    // param_enc is streamed exactly once -> evict-first (.cs) so L2 keeps h_prot.
    const float bias = b1[0];
    float4 wreg[4];
    #pragma unroll
    for (int k = 0; k < 4; k++)
        wreg[k] = *reinterpret_cast<const float4*>(w1 + 4 * e8 + 32 * k);

    {
        const float* pr0 = pe + (size_t)(4 * wid + rsub) * PP + 4 * e8;
        const int rstep = 64 * PP;                 // floats per t-step

        float4 bufA[4], bufB[4];
        #pragma unroll
        for (int k = 0; k < 4; k++)
            bufA[k] = __ldcs(reinterpret_cast<const float4*>(pr0 + 32 * k));

        #pragma unroll
        for (int t = 0; t < 16; t++) {
            float4* cur = (t & 1) ? bufB : bufA;
            float4* nxt = (t & 1) ? bufA : bufB;
            if (t < 15) {
                const float* pn = pr0 + (size_t)(t + 1) * rstep;
                #pragma unroll
                for (int k = 0; k < 4; k++)
                    nxt[k] = __ldcs(reinterpret_cast<const float4*>(pn + 32 * k));
            }
            // tree-form dot: 4 independent partials, then pairwise add
            float p0 = cur[0].x * wreg[0].x + cur[0].y * wreg[0].y
                     + cur[0].z * wreg[0].z + cur[0].w * wreg[0].w;
            float p1 = cur[1].x * wreg[1].x + cur[1].y * wreg[1].y
                     + cur[1].z * wreg[1].z + cur[1].w * wreg[1].w;
            float p2 = cur[2].x * wreg[2].x + cur[2].y * wreg[2].y
                     + cur[2].z * wreg[2].z + cur[2].w * wreg[2].w;
            float p3 = cur[3].x * wreg[3].x + cur[3].y * wreg[3].y
                     + cur[3].z * wreg[3].z + cur[3].w * wreg[3].w;
            float s = (p0 + p1) + (p2 + p3);
            s += __shfl_xor_sync(0xffffffffu, s, 1);
            s += __shfl_xor_sync(0xffffffffu, s, 2);
            s += __shfl_xor_sync(0xffffffffu, s, 4);
            if (e8 == 0) {
                const int row = t * 64 + 4 * wid + rsub;
                ent[row].x = s + bias;
            }
        }
    }
    __syncthreads();

    // ---- phase 2: gather + REGISTER accumulate ----
    // Warp owns output rows with il>>3 == wid; lane owns 4 cols (float4).
    // All lanes process the same entry -> il&7 warp-uniform -> switch.
    float4 acc[8];
    #pragma unroll
    for (int r = 0; r < 8; r++) acc[r] = make_float4(0.f, 0.f, 0.f, 0.f);

    {
        const int pb = protein_idx[b];
        const float* hp = h_prot + (size_t)pb * LPROT * HH + 4 * lane;
        unsigned char* wl = wlist + wid * 256;

        for (int blk = 0; blk < 4; blk++) {
            const int j0b = blk * 256;
            // pass A: ballot-compact my entries (deterministic order)
            int cnt = 0;
            #pragma unroll
            for (int j0 = 0; j0 < 256; j0 += 32) {
                float2 e = ent[j0b + j0 + lane];
                unsigned ix = __float_as_uint(e.y);
                bool mine = (e.x > 0.f) && (((ix & 0xffffu) >> 3) == (unsigned)wid);
                unsigned bal = __ballot_sync(0xffffffffu, mine);
                int pos = cnt + __popc(bal & ((1u << lane) - 1u));
                if (mine) wl[pos] = (unsigned char)(j0 + lane);
                cnt += __popc(bal);
            }
            // pass B: batches of 4 gathers in flight
            for (int i = 0; i < cnt; i += 4) {
                float    gq[4];
                unsigned ilp = 0;
                float4   hq[4];
                #pragma unroll
                for (int q = 0; q < 4; q++) {
                    const bool v = (i + q) < cnt;
                    const int jj = j0b + (int)wl[v ? (i + q) : i];
                    float2 e = ent[jj];
                    unsigned ix = __float_as_uint(e.y);
                    gq[q] = v ? e.x : 0.f;
                    ilp |= (ix & 7u) << (8 * q);
                    hq[q] = *reinterpret_cast<const float4*>(hp + (size_t)(ix >> 16) * HH);
                }
                #pragma unroll
                for (int q = 0; q < 4; q++) {
                    const float  g = gq[q];
                    const float4 h = hq[q];
                    #define ACC_CASE(R) case R: \
                        acc[R].x += g * h.x; acc[R].y += g * h.y; \
                        acc[R].z += g * h.z; acc[R].w += g * h.w; break;
                    switch ((ilp >> (8 * q)) & 7u) {
                        ACC_CASE(0) ACC_CASE(1) ACC_CASE(2) ACC_CASE(3)
                        ACC_CASE(4) ACC_CASE(5) ACC_CASE(6) ACC_CASE(7)
                    }
                    #undef ACC_CASE
                }
            }
        }
    }

    // ---- phase 3: register -> global writeout, streaming stores ----
    {
        const int off = lig_offsets[b];
        float* ob = out + (size_t)off * HH + 4 * lane;
        #pragma unroll
        for (int r = 0; r < 8; r++)
            __stcs(reinterpret_cast<float4*>(ob + (8 * wid + r) * HH), acc[r]);
    }
}

extern "C" void kernel_launch(void* const* d_in, const int* in_sizes, int n_in,
                              void* d_out, int out_size)
{
    (void)in_sizes; (void)n_in; (void)out_size;

    cudaFuncSetAttribute(ile_kernel,
                         cudaFuncAttributeMaxDynamicSharedMemorySize, SMEM_B);

    ile_kernel<<<BB, 512, SMEM_B>>>(
        (const float*)d_in[0], (const float*)d_in[1],
        (const float*)d_in[2], (const float*)d_in[3],
        (const int*)d_in[4],   (const int*)d_in[5],
        (const int*)d_in[6],   (const int*)d_in[7],
        (float*)d_out);
}